// round 1
// baseline (speedup 1.0000x reference)
#include <cuda_runtime.h>
#include <cuda_bf16.h>
#include <math.h>

// ---------------- problem constants ----------------
#define BATCH 2
#define SEQL 2048
#define TOK (BATCH * SEQL)          // 4096
#define DM 1024
#define DI 2048
#define NH 32
#define HD 64
#define DS 64
#define DCONV 4
#define CONVD (DI + 2 * DS)         // 2176
#define DIP (2 * DI + 2 * DS + NH)  // 4256
#define DMLP (4 * DM)               // 4096
#define EPSV 1e-5f

// ---------------- scratch (allocation-free) ----------------
__device__ float g_ln1[TOK * DM];
__device__ float g_zx[TOK * DIP];
__device__ float g_xbc[TOK * CONVD];
__device__ float g_dt[TOK * NH];
__device__ float g_y[TOK * DI];
__device__ float g_yn[TOK * DI];
__device__ float g_x1[TOK * DM];
__device__ float g_h2[TOK * DM];
__device__ float g_mid[TOK * DMLP];

// ---------------- helpers ----------------
__device__ __forceinline__ float block_reduce_sum(float v, float* smem) {
    int lane = threadIdx.x & 31, wid = threadIdx.x >> 5;
    #pragma unroll
    for (int o = 16; o; o >>= 1) v += __shfl_xor_sync(0xffffffffu, v, o);
    if (lane == 0) smem[wid] = v;
    __syncthreads();
    float r = (threadIdx.x < (blockDim.x >> 5)) ? smem[threadIdx.x] : 0.f;
    if (wid == 0) {
        #pragma unroll
        for (int o = 16; o; o >>= 1) r += __shfl_xor_sync(0xffffffffu, r, o);
        if (lane == 0) smem[0] = r;
    }
    __syncthreads();
    r = smem[0];
    __syncthreads();
    return r;
}

// ---------------- LayerNorm over DM=1024, one block per row ----------------
__global__ void ln_kernel(const float* __restrict__ x, const float* __restrict__ w,
                          const float* __restrict__ b, float* __restrict__ out) {
    __shared__ float smem[32];
    int row = blockIdx.x;
    const float* xr = x + (size_t)row * DM;
    float v[4];
    float s = 0.f;
    #pragma unroll
    for (int i = 0; i < 4; i++) { v[i] = xr[threadIdx.x + i * 256]; s += v[i]; }
    float mean = block_reduce_sum(s, smem) * (1.f / DM);
    float s2 = 0.f;
    #pragma unroll
    for (int i = 0; i < 4; i++) { float d = v[i] - mean; s2 += d * d; }
    float var = block_reduce_sum(s2, smem) * (1.f / DM);
    float rs = rsqrtf(var + EPSV);
    #pragma unroll
    for (int i = 0; i < 4; i++) {
        int c = threadIdx.x + i * 256;
        out[(size_t)row * DM + c] = (v[i] - mean) * rs * w[c] + b[c];
    }
}

// ---------------- SGEMM: C[M,N] = A[M,K] @ W[N,K]^T, fused epilogue ----------------
// act: 0=none, 1=exact gelu
#define BM 64
#define BN 64
#define BK 16
__global__ void __launch_bounds__(256) gemm_kernel(
    const float* __restrict__ A, const float* __restrict__ W, float* __restrict__ C,
    int M, int N, int K,
    const float* __restrict__ bias, const float* __restrict__ res, int act) {
    __shared__ float As[BK][BM];
    __shared__ float Bs[BK][BN];
    int tx = threadIdx.x, ty = threadIdx.y;       // 16x16
    int tid = ty * 16 + tx;
    int m0 = blockIdx.y * BM, n0 = blockIdx.x * BN;
    int lr = tid >> 2;           // 0..63
    int lk = (tid & 3) * 4;      // 0,4,8,12
    float acc[4][4] = {};
    for (int k0 = 0; k0 < K; k0 += BK) {
        // load A tile (M always multiple of 64 here)
        float4 av = *reinterpret_cast<const float4*>(&A[(size_t)(m0 + lr) * K + k0 + lk]);
        As[lk + 0][lr] = av.x; As[lk + 1][lr] = av.y;
        As[lk + 2][lr] = av.z; As[lk + 3][lr] = av.w;
        // load W tile with N bound-check
        float4 wv = make_float4(0.f, 0.f, 0.f, 0.f);
        if (n0 + lr < N)
            wv = *reinterpret_cast<const float4*>(&W[(size_t)(n0 + lr) * K + k0 + lk]);
        Bs[lk + 0][lr] = wv.x; Bs[lk + 1][lr] = wv.y;
        Bs[lk + 2][lr] = wv.z; Bs[lk + 3][lr] = wv.w;
        __syncthreads();
        #pragma unroll
        for (int k = 0; k < BK; k++) {
            float4 a = *reinterpret_cast<const float4*>(&As[k][ty * 4]);
            float4 bq = *reinterpret_cast<const float4*>(&Bs[k][tx * 4]);
            float ar[4] = {a.x, a.y, a.z, a.w};
            float br[4] = {bq.x, bq.y, bq.z, bq.w};
            #pragma unroll
            for (int i = 0; i < 4; i++)
                #pragma unroll
                for (int j = 0; j < 4; j++)
                    acc[i][j] = fmaf(ar[i], br[j], acc[i][j]);
        }
        __syncthreads();
    }
    #pragma unroll
    for (int i = 0; i < 4; i++) {
        int m = m0 + ty * 4 + i;
        #pragma unroll
        for (int j = 0; j < 4; j++) {
            int n = n0 + tx * 4 + j;
            if (n < N) {
                float v = acc[i][j];
                if (bias) v += bias[n];
                if (act == 1) v = 0.5f * v * (1.f + erff(v * 0.70710678118654752f));
                if (res) v += res[(size_t)m * N + n];
                C[(size_t)m * N + n] = v;
            }
        }
    }
}

// ---------------- depthwise causal conv + silu on xBC ----------------
__global__ void conv_silu_kernel(const float* __restrict__ zx, const float* __restrict__ cw,
                                 const float* __restrict__ cb, float* __restrict__ out) {
    int idx = blockIdx.x * blockDim.x + threadIdx.x;
    if (idx >= TOK * CONVD) return;
    int c = idx % CONVD;
    int t = idx / CONVD;
    int b = t / SEQL, l = t % SEQL;
    float acc = cb[c];
    #pragma unroll
    for (int k = 0; k < DCONV; k++) {
        int lk = l - (DCONV - 1) + k;
        if (lk >= 0)
            acc = fmaf(zx[((size_t)(b * SEQL + lk)) * DIP + DI + c], cw[c * DCONV + k], acc);
    }
    // silu
    out[idx] = acc * (1.f / (1.f + __expf(-acc)));
}

// ---------------- dt = softplus(raw + dt_bias) ----------------
__global__ void dt_kernel(const float* __restrict__ zx, const float* __restrict__ dtb,
                          float* __restrict__ dt) {
    int idx = blockIdx.x * blockDim.x + threadIdx.x;
    if (idx >= TOK * NH) return;
    int h = idx % NH;
    float v = zx[(size_t)(idx / NH) * DIP + DI + CONVD + h] + dtb[h];
    dt[idx] = (v > 20.f) ? v : log1pf(expf(v));
}

// ---------------- selective scan: one block per (b,h), warp per 2 p-rows ----------------
__global__ void __launch_bounds__(1024) scan_kernel(
    const float* __restrict__ xbc, const float* __restrict__ dtv,
    const float* __restrict__ A_log, const float* __restrict__ Dv,
    float* __restrict__ y) {
    int b = blockIdx.x / NH;
    int hh = blockIdx.x % NH;
    int warp = threadIdx.x >> 5, lane = threadIdx.x & 31;
    int p0 = warp, p1 = warp + 32;
    float A = -__expf(A_log[hh]);
    float Dh = Dv[hh];
    float h00 = 0.f, h01 = 0.f, h10 = 0.f, h11 = 0.f;
    const float* xb = xbc + (size_t)b * SEQL * CONVD;
    const float* dtp = dtv + (size_t)b * SEQL * NH + hh;
    float* yb = y + (size_t)b * SEQL * DI + hh * HD;
    for (int t = 0; t < SEQL; t++) {
        const float* row = xb + (size_t)t * CONVD;
        float dt = __ldg(dtp + (size_t)t * NH);
        float dA = __expf(dt * A);
        float B0 = __ldg(row + DI + lane);
        float B1 = __ldg(row + DI + 32 + lane);
        float C0 = __ldg(row + DI + DS + lane);
        float C1 = __ldg(row + DI + DS + 32 + lane);
        float x0 = __ldg(row + hh * HD + p0);
        float x1 = __ldg(row + hh * HD + p1);
        float dx0 = dt * x0, dx1 = dt * x1;
        h00 = fmaf(h00, dA, dx0 * B0);
        h01 = fmaf(h01, dA, dx0 * B1);
        h10 = fmaf(h10, dA, dx1 * B0);
        h11 = fmaf(h11, dA, dx1 * B1);
        float y0 = h00 * C0 + h01 * C1;
        float y1 = h10 * C0 + h11 * C1;
        #pragma unroll
        for (int o = 16; o; o >>= 1) {
            y0 += __shfl_xor_sync(0xffffffffu, y0, o);
            y1 += __shfl_xor_sync(0xffffffffu, y1, o);
        }
        if (lane == 0) {
            yb[(size_t)t * DI + p0] = y0 + Dh * x0;
            yb[(size_t)t * DI + p1] = y1 + Dh * x1;
        }
    }
}

// ---------------- gated RMSNorm over DI=2048 ----------------
__global__ void rms_gate_kernel(const float* __restrict__ ysrc, const float* __restrict__ zx,
                                const float* __restrict__ nw, float* __restrict__ out) {
    __shared__ float smem[32];
    int row = blockIdx.x;
    float v[8];
    float s = 0.f;
    #pragma unroll
    for (int i = 0; i < 8; i++) {
        int c = threadIdx.x + i * 256;
        float z = zx[(size_t)row * DIP + c];
        float g = z * (1.f / (1.f + __expf(-z)));
        float vv = ysrc[(size_t)row * DI + c] * g;
        v[i] = vv;
        s += vv * vv;
    }
    float ms = block_reduce_sum(s, smem) * (1.f / DI);
    float rs = rsqrtf(ms + EPSV);
    #pragma unroll
    for (int i = 0; i < 8; i++) {
        int c = threadIdx.x + i * 256;
        out[(size_t)row * DI + c] = v[i] * rs * nw[c];
    }
}

// ---------------- launch ----------------
extern "C" void kernel_launch(void* const* d_in, const int* in_sizes, int n_in,
                              void* d_out, int out_size) {
    const float* x        = (const float*)d_in[0];
    const float* ln1_w    = (const float*)d_in[1];
    const float* ln1_b    = (const float*)d_in[2];
    const float* in_proj  = (const float*)d_in[3];
    const float* conv_w   = (const float*)d_in[4];
    const float* conv_b   = (const float*)d_in[5];
    const float* dt_bias  = (const float*)d_in[6];
    const float* A_log    = (const float*)d_in[7];
    const float* Dv       = (const float*)d_in[8];
    const float* norm_w   = (const float*)d_in[9];
    const float* out_proj = (const float*)d_in[10];
    const float* ln2_w    = (const float*)d_in[11];
    const float* ln2_b    = (const float*)d_in[12];
    const float* mlp_w1   = (const float*)d_in[13];
    const float* mlp_b1   = (const float*)d_in[14];
    const float* mlp_w2   = (const float*)d_in[15];
    const float* mlp_b2   = (const float*)d_in[16];
    float* out = (float*)d_out;

    float *p_ln1, *p_zx, *p_xbc, *p_dt, *p_y, *p_yn, *p_x1, *p_h2, *p_mid;
    cudaGetSymbolAddress((void**)&p_ln1, g_ln1);
    cudaGetSymbolAddress((void**)&p_zx, g_zx);
    cudaGetSymbolAddress((void**)&p_xbc, g_xbc);
    cudaGetSymbolAddress((void**)&p_dt, g_dt);
    cudaGetSymbolAddress((void**)&p_y, g_y);
    cudaGetSymbolAddress((void**)&p_yn, g_yn);
    cudaGetSymbolAddress((void**)&p_x1, g_x1);
    cudaGetSymbolAddress((void**)&p_h2, g_h2);
    cudaGetSymbolAddress((void**)&p_mid, g_mid);

    dim3 tgemm(16, 16);

    // 1. LN1
    ln_kernel<<<TOK, 256>>>(x, ln1_w, ln1_b, p_ln1);
    // 2. in_proj: [4096,1024] @ [4256,1024]^T -> [4096,4256]
    gemm_kernel<<<dim3((DIP + BN - 1) / BN, TOK / BM), tgemm>>>(
        p_ln1, in_proj, p_zx, TOK, DIP, DM, nullptr, nullptr, 0);
    // 3. conv + silu
    {
        int total = TOK * CONVD;
        conv_silu_kernel<<<(total + 255) / 256, 256>>>(p_zx, conv_w, conv_b, p_xbc);
    }
    // 4. dt
    dt_kernel<<<(TOK * NH + 255) / 256, 256>>>(p_zx, dt_bias, p_dt);
    // 5. selective scan
    scan_kernel<<<BATCH * NH, 1024>>>(p_xbc, p_dt, A_log, Dv, p_y);
    // 6. gated rmsnorm
    rms_gate_kernel<<<TOK, 256>>>(p_y, p_zx, norm_w, p_yn);
    // 7. out_proj + residual(x) -> x1
    gemm_kernel<<<dim3(DM / BN, TOK / BM), tgemm>>>(
        p_yn, out_proj, p_x1, TOK, DM, DI, nullptr, x, 0);
    // 8. LN2
    ln_kernel<<<TOK, 256>>>(p_x1, ln2_w, ln2_b, p_h2);
    // 9. MLP1 + bias + gelu
    gemm_kernel<<<dim3(DMLP / BN, TOK / BM), tgemm>>>(
        p_h2, mlp_w1, p_mid, TOK, DMLP, DM, mlp_b1, nullptr, 1);
    // 10. MLP2 + bias + residual(x1) -> out
    gemm_kernel<<<dim3(DM / BN, TOK / BM), tgemm>>>(
        p_mid, mlp_w2, out, TOK, DM, DMLP, mlp_b2, p_x1, 0);
}

// round 2
// speedup vs baseline: 2.0990x; 2.0990x over previous
#include <cuda_runtime.h>
#include <cuda_bf16.h>
#include <math.h>
#include <stdint.h>

// ---------------- problem constants ----------------
#define BATCH 2
#define SEQL 2048
#define TOK (BATCH * SEQL)          // 4096
#define DM 1024
#define DI 2048
#define NH 32
#define HD 64
#define DS 64
#define DCONV 4
#define CONVD (DI + 2 * DS)         // 2176
#define DIP (2 * DI + 2 * DS + NH)  // 4256
#define DMLP (4 * DM)               // 4096
#define EPSV 1e-5f

// ---------------- scratch (allocation-free) ----------------
__device__ float g_ln1[TOK * DM];
__device__ float g_zx[TOK * DIP];
__device__ float g_xbc[TOK * CONVD];
__device__ float g_dt[TOK * NH];
__device__ float g_y[TOK * DI];
__device__ float g_yn[TOK * DI];
__device__ float g_x1[TOK * DM];
__device__ float g_h2[TOK * DM];
__device__ float g_mid[TOK * DMLP];

// ---------------- helpers ----------------
__device__ __forceinline__ float block_reduce_sum(float v, float* smem) {
    int lane = threadIdx.x & 31, wid = threadIdx.x >> 5;
    #pragma unroll
    for (int o = 16; o; o >>= 1) v += __shfl_xor_sync(0xffffffffu, v, o);
    if (lane == 0) smem[wid] = v;
    __syncthreads();
    float r = (threadIdx.x < (blockDim.x >> 5)) ? smem[threadIdx.x] : 0.f;
    if (wid == 0) {
        #pragma unroll
        for (int o = 16; o; o >>= 1) r += __shfl_xor_sync(0xffffffffu, r, o);
        if (lane == 0) smem[0] = r;
    }
    __syncthreads();
    r = smem[0];
    __syncthreads();
    return r;
}

__device__ __forceinline__ uint32_t f2tf(float f) {
    uint32_t u;
    asm("cvt.rna.tf32.f32 %0, %1;" : "=r"(u) : "f"(f));
    return u;
}

__device__ __forceinline__ void mma_tf32(float* c, uint32_t a0, uint32_t a1,
                                         uint32_t a2, uint32_t a3,
                                         uint32_t b0, uint32_t b1) {
    asm volatile(
        "mma.sync.aligned.m16n8k8.row.col.f32.tf32.tf32.f32 "
        "{%0,%1,%2,%3}, {%4,%5,%6,%7}, {%8,%9}, {%0,%1,%2,%3};"
        : "+f"(c[0]), "+f"(c[1]), "+f"(c[2]), "+f"(c[3])
        : "r"(a0), "r"(a1), "r"(a2), "r"(a3), "r"(b0), "r"(b1));
}

// ---------------- LayerNorm over DM=1024, one block per row ----------------
__global__ void ln_kernel(const float* __restrict__ x, const float* __restrict__ w,
                          const float* __restrict__ b, float* __restrict__ out) {
    __shared__ float smem[32];
    int row = blockIdx.x;
    const float* xr = x + (size_t)row * DM;
    float v[4];
    float s = 0.f;
    #pragma unroll
    for (int i = 0; i < 4; i++) { v[i] = xr[threadIdx.x + i * 256]; s += v[i]; }
    float mean = block_reduce_sum(s, smem) * (1.f / DM);
    float s2 = 0.f;
    #pragma unroll
    for (int i = 0; i < 4; i++) { float d = v[i] - mean; s2 += d * d; }
    float var = block_reduce_sum(s2, smem) * (1.f / DM);
    float rs = rsqrtf(var + EPSV);
    #pragma unroll
    for (int i = 0; i < 4; i++) {
        int c = threadIdx.x + i * 256;
        out[(size_t)row * DM + c] = (v[i] - mean) * rs * w[c] + b[c];
    }
}

// ---------------- Tensor-core tf32 GEMM ----------------
// C[M,N] = A[M,K] @ W[N,K]^T, fused epilogue. act: 0=none, 1=exact gelu.
// CTA tile 128x128, 128 threads (2x2 warps of 64x64), K-chunk 32.
// Smem layout [row][32] fp32->tf32 with XOR swizzle col' = k ^ (4*(row&7)):
// coalesced LDG.128, conflict-free STS.128, conflict-free fragment LDS.
__global__ void __launch_bounds__(128) gemm_tc_kernel(
    const float* __restrict__ A, const float* __restrict__ W, float* __restrict__ C,
    int M, int N, int K,
    const float* __restrict__ bias, const float* __restrict__ res, int act) {
    __shared__ uint32_t As[128 * 32];
    __shared__ uint32_t Bs[128 * 32];

    const int tid = threadIdx.x;
    const int lane = tid & 31;
    const int warp = tid >> 5;
    const int g = lane >> 2;   // group id (0..7)
    const int t = lane & 3;    // thread in group (0..3)
    const int wm = warp >> 1;  // 0..1
    const int wn = warp & 1;   // 0..1
    const int m0 = blockIdx.y * 128;
    const int n0 = blockIdx.x * 128;

    float c[4][8][4] = {};

    for (int k0 = 0; k0 < K; k0 += 32) {
        if (k0) __syncthreads();
        // ---- load A,B tiles (each thread: 8 rows' float4 per operand) ----
        #pragma unroll
        for (int i = 0; i < 8; i++) {
            int lin = tid + 128 * i;
            int kq = lin & 7;        // float4 index within k-chunk
            int r  = lin >> 3;       // tile row 0..127
            uint32_t col = (uint32_t)((4 * kq) ^ (4 * (r & 7)));
            {
                float4 av = *reinterpret_cast<const float4*>(
                    &A[(size_t)(m0 + r) * K + k0 + kq * 4]);
                uint4 pv;
                pv.x = f2tf(av.x); pv.y = f2tf(av.y);
                pv.z = f2tf(av.z); pv.w = f2tf(av.w);
                *reinterpret_cast<uint4*>(&As[r * 32 + col]) = pv;
            }
            {
                int n = n0 + r;
                float4 wv = make_float4(0.f, 0.f, 0.f, 0.f);
                if (n < N)
                    wv = *reinterpret_cast<const float4*>(
                        &W[(size_t)n * K + k0 + kq * 4]);
                uint4 pv;
                pv.x = f2tf(wv.x); pv.y = f2tf(wv.y);
                pv.z = f2tf(wv.z); pv.w = f2tf(wv.w);
                *reinterpret_cast<uint4*>(&Bs[r * 32 + col]) = pv;
            }
        }
        __syncthreads();
        // ---- 4 k8-steps of mma ----
        const uint32_t xg = 4 * (uint32_t)g;
        #pragma unroll
        for (int ks = 0; ks < 4; ks++) {
            const uint32_t kk = (uint32_t)(ks * 8 + t);
            uint32_t bf[8][2];
            #pragma unroll
            for (int jt = 0; jt < 8; jt++) {
                int colr = wn * 64 + jt * 8 + g;
                bf[jt][0] = Bs[colr * 32 + (kk ^ xg)];
                bf[jt][1] = Bs[colr * 32 + ((kk + 4) ^ xg)];
            }
            #pragma unroll
            for (int it = 0; it < 4; it++) {
                int r0 = wm * 64 + it * 16 + g;
                int r1 = r0 + 8;
                uint32_t a0 = As[r0 * 32 + (kk ^ xg)];
                uint32_t a1 = As[r1 * 32 + (kk ^ xg)];
                uint32_t a2 = As[r0 * 32 + ((kk + 4) ^ xg)];
                uint32_t a3 = As[r1 * 32 + ((kk + 4) ^ xg)];
                #pragma unroll
                for (int jt = 0; jt < 8; jt++)
                    mma_tf32(c[it][jt], a0, a1, a2, a3, bf[jt][0], bf[jt][1]);
            }
        }
    }

    // ---- epilogue ----
    #pragma unroll
    for (int it = 0; it < 4; it++) {
        int r0 = m0 + wm * 64 + it * 16 + g;
        int r1 = r0 + 8;
        #pragma unroll
        for (int jt = 0; jt < 8; jt++) {
            int nn = n0 + wn * 64 + jt * 8 + 2 * t;
            if (nn < N) {
                float v[4] = {c[it][jt][0], c[it][jt][1], c[it][jt][2], c[it][jt][3]};
                if (bias) {
                    float b0 = bias[nn], b1 = bias[nn + 1];
                    v[0] += b0; v[1] += b1; v[2] += b0; v[3] += b1;
                }
                if (act == 1) {
                    #pragma unroll
                    for (int q = 0; q < 4; q++)
                        v[q] = 0.5f * v[q] * (1.f + erff(v[q] * 0.70710678118654752f));
                }
                if (res) {
                    v[0] += res[(size_t)r0 * N + nn];
                    v[1] += res[(size_t)r0 * N + nn + 1];
                    v[2] += res[(size_t)r1 * N + nn];
                    v[3] += res[(size_t)r1 * N + nn + 1];
                }
                *reinterpret_cast<float2*>(&C[(size_t)r0 * N + nn]) = make_float2(v[0], v[1]);
                *reinterpret_cast<float2*>(&C[(size_t)r1 * N + nn]) = make_float2(v[2], v[3]);
            }
        }
    }
}

// ---------------- depthwise causal conv + silu on xBC ----------------
__global__ void conv_silu_kernel(const float* __restrict__ zx, const float* __restrict__ cw,
                                 const float* __restrict__ cb, float* __restrict__ out) {
    int idx = blockIdx.x * blockDim.x + threadIdx.x;
    if (idx >= TOK * CONVD) return;
    int c = idx % CONVD;
    int t = idx / CONVD;
    int b = t / SEQL, l = t % SEQL;
    float acc = cb[c];
    #pragma unroll
    for (int k = 0; k < DCONV; k++) {
        int lk = l - (DCONV - 1) + k;
        if (lk >= 0)
            acc = fmaf(zx[((size_t)(b * SEQL + lk)) * DIP + DI + c], cw[c * DCONV + k], acc);
    }
    out[idx] = acc * (1.f / (1.f + __expf(-acc)));
}

// ---------------- dt = softplus(raw + dt_bias) ----------------
__global__ void dt_kernel(const float* __restrict__ zx, const float* __restrict__ dtb,
                          float* __restrict__ dt) {
    int idx = blockIdx.x * blockDim.x + threadIdx.x;
    if (idx >= TOK * NH) return;
    int h = idx % NH;
    float v = zx[(size_t)(idx / NH) * DIP + DI + CONVD + h] + dtb[h];
    dt[idx] = (v > 20.f) ? v : log1pf(expf(v));
}

// ---------------- selective scan: one block per (b,h), warp per 2 p-rows ----------------
__global__ void __launch_bounds__(1024) scan_kernel(
    const float* __restrict__ xbc, const float* __restrict__ dtv,
    const float* __restrict__ A_log, const float* __restrict__ Dv,
    float* __restrict__ y) {
    int b = blockIdx.x / NH;
    int hh = blockIdx.x % NH;
    int warp = threadIdx.x >> 5, lane = threadIdx.x & 31;
    int p0 = warp, p1 = warp + 32;
    float A = -__expf(A_log[hh]);
    float Dh = Dv[hh];
    float h00 = 0.f, h01 = 0.f, h10 = 0.f, h11 = 0.f;
    const float* xb = xbc + (size_t)b * SEQL * CONVD;
    const float* dtp = dtv + (size_t)b * SEQL * NH + hh;
    float* yb = y + (size_t)b * SEQL * DI + hh * HD;
    for (int t = 0; t < SEQL; t++) {
        const float* row = xb + (size_t)t * CONVD;
        float dt = __ldg(dtp + (size_t)t * NH);
        float dA = __expf(dt * A);
        float B0 = __ldg(row + DI + lane);
        float B1 = __ldg(row + DI + 32 + lane);
        float C0 = __ldg(row + DI + DS + lane);
        float C1 = __ldg(row + DI + DS + 32 + lane);
        float x0 = __ldg(row + hh * HD + p0);
        float x1 = __ldg(row + hh * HD + p1);
        float dx0 = dt * x0, dx1 = dt * x1;
        h00 = fmaf(h00, dA, dx0 * B0);
        h01 = fmaf(h01, dA, dx0 * B1);
        h10 = fmaf(h10, dA, dx1 * B0);
        h11 = fmaf(h11, dA, dx1 * B1);
        float y0 = h00 * C0 + h01 * C1;
        float y1 = h10 * C0 + h11 * C1;
        #pragma unroll
        for (int o = 16; o; o >>= 1) {
            y0 += __shfl_xor_sync(0xffffffffu, y0, o);
            y1 += __shfl_xor_sync(0xffffffffu, y1, o);
        }
        if (lane == 0) {
            yb[(size_t)t * DI + p0] = y0 + Dh * x0;
            yb[(size_t)t * DI + p1] = y1 + Dh * x1;
        }
    }
}

// ---------------- gated RMSNorm over DI=2048 ----------------
__global__ void rms_gate_kernel(const float* __restrict__ ysrc, const float* __restrict__ zx,
                                const float* __restrict__ nw, float* __restrict__ out) {
    __shared__ float smem[32];
    int row = blockIdx.x;
    float v[8];
    float s = 0.f;
    #pragma unroll
    for (int i = 0; i < 8; i++) {
        int c = threadIdx.x + i * 256;
        float z = zx[(size_t)row * DIP + c];
        float g = z * (1.f / (1.f + __expf(-z)));
        float vv = ysrc[(size_t)row * DI + c] * g;
        v[i] = vv;
        s += vv * vv;
    }
    float ms = block_reduce_sum(s, smem) * (1.f / DI);
    float rs = rsqrtf(ms + EPSV);
    #pragma unroll
    for (int i = 0; i < 8; i++) {
        int c = threadIdx.x + i * 256;
        out[(size_t)row * DI + c] = v[i] * rs * nw[c];
    }
}

// ---------------- launch ----------------
extern "C" void kernel_launch(void* const* d_in, const int* in_sizes, int n_in,
                              void* d_out, int out_size) {
    const float* x        = (const float*)d_in[0];
    const float* ln1_w    = (const float*)d_in[1];
    const float* ln1_b    = (const float*)d_in[2];
    const float* in_proj  = (const float*)d_in[3];
    const float* conv_w   = (const float*)d_in[4];
    const float* conv_b   = (const float*)d_in[5];
    const float* dt_bias  = (const float*)d_in[6];
    const float* A_log    = (const float*)d_in[7];
    const float* Dv       = (const float*)d_in[8];
    const float* norm_w   = (const float*)d_in[9];
    const float* out_proj = (const float*)d_in[10];
    const float* ln2_w    = (const float*)d_in[11];
    const float* ln2_b    = (const float*)d_in[12];
    const float* mlp_w1   = (const float*)d_in[13];
    const float* mlp_b1   = (const float*)d_in[14];
    const float* mlp_w2   = (const float*)d_in[15];
    const float* mlp_b2   = (const float*)d_in[16];
    float* out = (float*)d_out;

    float *p_ln1, *p_zx, *p_xbc, *p_dt, *p_y, *p_yn, *p_x1, *p_h2, *p_mid;
    cudaGetSymbolAddress((void**)&p_ln1, g_ln1);
    cudaGetSymbolAddress((void**)&p_zx, g_zx);
    cudaGetSymbolAddress((void**)&p_xbc, g_xbc);
    cudaGetSymbolAddress((void**)&p_dt, g_dt);
    cudaGetSymbolAddress((void**)&p_y, g_y);
    cudaGetSymbolAddress((void**)&p_yn, g_yn);
    cudaGetSymbolAddress((void**)&p_x1, g_x1);
    cudaGetSymbolAddress((void**)&p_h2, g_h2);
    cudaGetSymbolAddress((void**)&p_mid, g_mid);

    // 1. LN1
    ln_kernel<<<TOK, 256>>>(x, ln1_w, ln1_b, p_ln1);
    // 2. in_proj: [4096,1024] @ [4256,1024]^T -> [4096,4256]
    gemm_tc_kernel<<<dim3((DIP + 127) / 128, TOK / 128), 128>>>(
        p_ln1, in_proj, p_zx, TOK, DIP, DM, nullptr, nullptr, 0);
    // 3. conv + silu
    {
        int total = TOK * CONVD;
        conv_silu_kernel<<<(total + 255) / 256, 256>>>(p_zx, conv_w, conv_b, p_xbc);
    }
    // 4. dt
    dt_kernel<<<(TOK * NH + 255) / 256, 256>>>(p_zx, dt_bias, p_dt);
    // 5. selective scan
    scan_kernel<<<BATCH * NH, 1024>>>(p_xbc, p_dt, A_log, Dv, p_y);
    // 6. gated rmsnorm
    rms_gate_kernel<<<TOK, 256>>>(p_y, p_zx, norm_w, p_yn);
    // 7. out_proj + residual(x) -> x1
    gemm_tc_kernel<<<dim3(DM / 128, TOK / 128), 128>>>(
        p_yn, out_proj, p_x1, TOK, DM, DI, nullptr, x, 0);
    // 8. LN2
    ln_kernel<<<TOK, 256>>>(p_x1, ln2_w, ln2_b, p_h2);
    // 9. MLP1 + bias + gelu
    gemm_tc_kernel<<<dim3(DMLP / 128, TOK / 128), 128>>>(
        p_h2, mlp_w1, p_mid, TOK, DMLP, DM, mlp_b1, nullptr, 1);
    // 10. MLP2 + bias + residual(x1) -> out
    gemm_tc_kernel<<<dim3(DM / 128, TOK / 128), 128>>>(
        p_mid, mlp_w2, out, TOK, DM, DMLP, mlp_b2, p_x1, 0);
}

// round 8
// speedup vs baseline: 2.6338x; 1.2548x over previous
#include <cuda_runtime.h>
#include <cuda_bf16.h>
#include <math.h>
#include <stdint.h>

// ---------------- problem constants ----------------
#define BATCH 2
#define SEQL 2048
#define TOK (BATCH * SEQL)          // 4096
#define DM 1024
#define DI 2048
#define NH 32
#define HD 64
#define DS 64
#define DCONV 4
#define CONVD (DI + 2 * DS)         // 2176
#define DIP (2 * DI + 2 * DS + NH)  // 4256
#define DMLP (4 * DM)               // 4096
#define EPSV 1e-5f

// ---------------- scratch (allocation-free) ----------------
__device__ float g_ln1[TOK * DM];
__device__ float g_zx[TOK * DIP];
__device__ float g_xbc[TOK * CONVD];
__device__ float g_dt[TOK * NH];
__device__ float g_y[TOK * DI];    // scan partial, state half 0 (+ D*x term)
__device__ float g_y2[TOK * DI];   // scan partial, state half 1
__device__ float g_yn[TOK * DI];
__device__ float g_x1[TOK * DM];
__device__ float g_h2[TOK * DM];
__device__ float g_mid[TOK * DMLP];

// ---------------- helpers ----------------
__device__ __forceinline__ float block_reduce_sum(float v, float* smem) {
    int lane = threadIdx.x & 31, wid = threadIdx.x >> 5;
    #pragma unroll
    for (int o = 16; o; o >>= 1) v += __shfl_xor_sync(0xffffffffu, v, o);
    if (lane == 0) smem[wid] = v;
    __syncthreads();
    float r = (threadIdx.x < (blockDim.x >> 5)) ? smem[threadIdx.x] : 0.f;
    if (wid == 0) {
        #pragma unroll
        for (int o = 16; o; o >>= 1) r += __shfl_xor_sync(0xffffffffu, r, o);
        if (lane == 0) smem[0] = r;
    }
    __syncthreads();
    r = smem[0];
    __syncthreads();
    return r;
}

__device__ __forceinline__ uint32_t f2tf(float f) {
    uint32_t u;
    asm("cvt.rna.tf32.f32 %0, %1;" : "=r"(u) : "f"(f));
    return u;
}

__device__ __forceinline__ void mma_tf32(float* c, uint32_t a0, uint32_t a1,
                                         uint32_t a2, uint32_t a3,
                                         uint32_t b0, uint32_t b1) {
    asm volatile(
        "mma.sync.aligned.m16n8k8.row.col.f32.tf32.tf32.f32 "
        "{%0,%1,%2,%3}, {%4,%5,%6,%7}, {%8,%9}, {%0,%1,%2,%3};"
        : "+f"(c[0]), "+f"(c[1]), "+f"(c[2]), "+f"(c[3])
        : "r"(a0), "r"(a1), "r"(a2), "r"(a3), "r"(b0), "r"(b1));
}

// ---------------- LayerNorm over DM=1024, one block per row ----------------
__global__ void ln_kernel(const float* __restrict__ x, const float* __restrict__ w,
                          const float* __restrict__ b, float* __restrict__ out) {
    __shared__ float smem[32];
    int row = blockIdx.x;
    const float* xr = x + (size_t)row * DM;
    float v[4];
    float s = 0.f;
    #pragma unroll
    for (int i = 0; i < 4; i++) { v[i] = xr[threadIdx.x + i * 256]; s += v[i]; }
    float mean = block_reduce_sum(s, smem) * (1.f / DM);
    float s2 = 0.f;
    #pragma unroll
    for (int i = 0; i < 4; i++) { float d = v[i] - mean; s2 += d * d; }
    float var = block_reduce_sum(s2, smem) * (1.f / DM);
    float rs = rsqrtf(var + EPSV);
    #pragma unroll
    for (int i = 0; i < 4; i++) {
        int c = threadIdx.x + i * 256;
        out[(size_t)row * DM + c] = (v[i] - mean) * rs * w[c] + b[c];
    }
}

// ---------------- Tensor-core tf32 GEMM, double-buffered ----------------
// C[M,N] = A[M,K] @ W[N,K]^T, fused epilogue. act: 0=none, 1=exact gelu.
// CTA tile 128x128, 256 threads = 8 warps (4x2), warp tile 32x64, K-chunk 32.
// Smem [row][32] tf32, XOR swizzle col' = k ^ (4*(row&7)); two stages.
// Pipeline per chunk: LDG A(next) | mma ks0,1 | STS A | LDG B(next) | mma ks2,3 | STS B | sync.
__global__ void __launch_bounds__(256, 2) gemm_tc_kernel(
    const float* __restrict__ A, const float* __restrict__ W, float* __restrict__ C,
    int M, int N, int K,
    const float* __restrict__ bias, const float* __restrict__ res, int act) {
    __shared__ uint32_t As[2][128 * 32];
    __shared__ uint32_t Bs[2][128 * 32];

    const int tid = threadIdx.x;
    const int lane = tid & 31;
    const int warp = tid >> 5;
    const int g = lane >> 2;   // 0..7
    const int t = lane & 3;    // 0..3
    const int wm = warp >> 1;  // 0..3
    const int wn = warp & 1;   // 0..1
    const int m0 = blockIdx.y * 128;
    const int n0 = blockIdx.x * 128;

    // per-thread load coords: 4 float4 per operand per chunk
    int lkq[4], lr[4];
    #pragma unroll
    for (int i = 0; i < 4; i++) {
        int lin = tid + 256 * i;
        lkq[i] = lin & 7;
        lr[i] = lin >> 3;
    }

    float c[2][8][4] = {};
    float4 ra[4], rb[4];

    // prologue: fill stage 0
    #pragma unroll
    for (int i = 0; i < 4; i++) {
        ra[i] = *reinterpret_cast<const float4*>(&A[(size_t)(m0 + lr[i]) * K + lkq[i] * 4]);
        int n = n0 + lr[i];
        rb[i] = make_float4(0.f, 0.f, 0.f, 0.f);
        if (n < N)
            rb[i] = *reinterpret_cast<const float4*>(&W[(size_t)n * K + lkq[i] * 4]);
    }
    #pragma unroll
    for (int i = 0; i < 4; i++) {
        uint32_t col = (uint32_t)((4 * lkq[i]) ^ (4 * (lr[i] & 7)));
        uint4 pa, pb;
        pa.x = f2tf(ra[i].x); pa.y = f2tf(ra[i].y); pa.z = f2tf(ra[i].z); pa.w = f2tf(ra[i].w);
        pb.x = f2tf(rb[i].x); pb.y = f2tf(rb[i].y); pb.z = f2tf(rb[i].z); pb.w = f2tf(rb[i].w);
        *reinterpret_cast<uint4*>(&As[0][lr[i] * 32 + col]) = pa;
        *reinterpret_cast<uint4*>(&Bs[0][lr[i] * 32 + col]) = pb;
    }
    __syncthreads();

    const int nk = K / 32;
    int s = 0;
    const uint32_t xg = 4 * (uint32_t)g;

    for (int ck = 0; ck < nk; ck++) {
        const uint32_t* as = As[s];
        const uint32_t* bs = Bs[s];
        const int knext = (ck + 1) * 32;
        const bool more = (ck + 1) < nk;

        // prefetch next A
        if (more) {
            #pragma unroll
            for (int i = 0; i < 4; i++)
                ra[i] = *reinterpret_cast<const float4*>(
                    &A[(size_t)(m0 + lr[i]) * K + knext + lkq[i] * 4]);
        }
        // compute ks = 0,1
        #pragma unroll
        for (int ks = 0; ks < 2; ks++) {
            const uint32_t kk = (uint32_t)(ks * 8 + t);
            uint32_t bf[8][2];
            #pragma unroll
            for (int jt = 0; jt < 8; jt++) {
                int colr = wn * 64 + jt * 8 + g;
                bf[jt][0] = bs[colr * 32 + (kk ^ xg)];
                bf[jt][1] = bs[colr * 32 + ((kk + 4) ^ xg)];
            }
            #pragma unroll
            for (int it = 0; it < 2; it++) {
                int r0 = wm * 32 + it * 16 + g;
                int r1 = r0 + 8;
                uint32_t a0 = as[r0 * 32 + (kk ^ xg)];
                uint32_t a1 = as[r1 * 32 + (kk ^ xg)];
                uint32_t a2 = as[r0 * 32 + ((kk + 4) ^ xg)];
                uint32_t a3 = as[r1 * 32 + ((kk + 4) ^ xg)];
                #pragma unroll
                for (int jt = 0; jt < 8; jt++)
                    mma_tf32(c[it][jt], a0, a1, a2, a3, bf[jt][0], bf[jt][1]);
            }
        }
        // store next A, prefetch next B
        if (more) {
            #pragma unroll
            for (int i = 0; i < 4; i++) {
                uint32_t col = (uint32_t)((4 * lkq[i]) ^ (4 * (lr[i] & 7)));
                uint4 pa;
                pa.x = f2tf(ra[i].x); pa.y = f2tf(ra[i].y);
                pa.z = f2tf(ra[i].z); pa.w = f2tf(ra[i].w);
                *reinterpret_cast<uint4*>(&As[s ^ 1][lr[i] * 32 + col]) = pa;
            }
            #pragma unroll
            for (int i = 0; i < 4; i++) {
                int n = n0 + lr[i];
                rb[i] = make_float4(0.f, 0.f, 0.f, 0.f);
                if (n < N)
                    rb[i] = *reinterpret_cast<const float4*>(
                        &W[(size_t)n * K + knext + lkq[i] * 4]);
            }
        }
        // compute ks = 2,3
        #pragma unroll
        for (int ks = 2; ks < 4; ks++) {
            const uint32_t kk = (uint32_t)(ks * 8 + t);
            uint32_t bf[8][2];
            #pragma unroll
            for (int jt = 0; jt < 8; jt++) {
                int colr = wn * 64 + jt * 8 + g;
                bf[jt][0] = bs[colr * 32 + (kk ^ xg)];
                bf[jt][1] = bs[colr * 32 + ((kk + 4) ^ xg)];
            }
            #pragma unroll
            for (int it = 0; it < 2; it++) {
                int r0 = wm * 32 + it * 16 + g;
                int r1 = r0 + 8;
                uint32_t a0 = as[r0 * 32 + (kk ^ xg)];
                uint32_t a1 = as[r1 * 32 + (kk ^ xg)];
                uint32_t a2 = as[r0 * 32 + ((kk + 4) ^ xg)];
                uint32_t a3 = as[r1 * 32 + ((kk + 4) ^ xg)];
                #pragma unroll
                for (int jt = 0; jt < 8; jt++)
                    mma_tf32(c[it][jt], a0, a1, a2, a3, bf[jt][0], bf[jt][1]);
            }
        }
        // store next B
        if (more) {
            #pragma unroll
            for (int i = 0; i < 4; i++) {
                uint32_t col = (uint32_t)((4 * lkq[i]) ^ (4 * (lr[i] & 7)));
                uint4 pb;
                pb.x = f2tf(rb[i].x); pb.y = f2tf(rb[i].y);
                pb.z = f2tf(rb[i].z); pb.w = f2tf(rb[i].w);
                *reinterpret_cast<uint4*>(&Bs[s ^ 1][lr[i] * 32 + col]) = pb;
            }
        }
        __syncthreads();
        s ^= 1;
    }

    // ---- epilogue ----
    #pragma unroll
    for (int it = 0; it < 2; it++) {
        int r0 = m0 + wm * 32 + it * 16 + g;
        int r1 = r0 + 8;
        #pragma unroll
        for (int jt = 0; jt < 8; jt++) {
            int nn = n0 + wn * 64 + jt * 8 + 2 * t;
            if (nn < N) {
                float v[4] = {c[it][jt][0], c[it][jt][1], c[it][jt][2], c[it][jt][3]};
                if (bias) {
                    float b0 = bias[nn], b1 = bias[nn + 1];
                    v[0] += b0; v[1] += b1; v[2] += b0; v[3] += b1;
                }
                if (act == 1) {
                    #pragma unroll
                    for (int q = 0; q < 4; q++)
                        v[q] = 0.5f * v[q] * (1.f + erff(v[q] * 0.70710678118654752f));
                }
                if (res) {
                    v[0] += res[(size_t)r0 * N + nn];
                    v[1] += res[(size_t)r0 * N + nn + 1];
                    v[2] += res[(size_t)r1 * N + nn];
                    v[3] += res[(size_t)r1 * N + nn + 1];
                }
                *reinterpret_cast<float2*>(&C[(size_t)r0 * N + nn]) = make_float2(v[0], v[1]);
                *reinterpret_cast<float2*>(&C[(size_t)r1 * N + nn]) = make_float2(v[2], v[3]);
            }
        }
    }
}

// ---------------- depthwise causal conv + silu on xBC ----------------
__global__ void conv_silu_kernel(const float* __restrict__ zx, const float* __restrict__ cw,
                                 const float* __restrict__ cb, float* __restrict__ out) {
    int idx = blockIdx.x * blockDim.x + threadIdx.x;
    if (idx >= TOK * CONVD) return;
    int c = idx % CONVD;
    int t = idx / CONVD;
    int b = t / SEQL, l = t % SEQL;
    float acc = cb[c];
    #pragma unroll
    for (int k = 0; k < DCONV; k++) {
        int lk = l - (DCONV - 1) + k;
        if (lk >= 0)
            acc = fmaf(zx[((size_t)(b * SEQL + lk)) * DIP + DI + c], cw[c * DCONV + k], acc);
    }
    out[idx] = acc * (1.f / (1.f + __expf(-acc)));
}

// ---------------- dt = softplus(raw + dt_bias) ----------------
__global__ void dt_kernel(const float* __restrict__ zx, const float* __restrict__ dtb,
                          float* __restrict__ dt) {
    int idx = blockIdx.x * blockDim.x + threadIdx.x;
    if (idx >= TOK * NH) return;
    int h = idx % NH;
    float v = zx[(size_t)(idx / NH) * DIP + DI + CONVD + h] + dtb[h];
    dt[idx] = (v > 20.f) ? v : log1pf(expf(v));
}

// ---------------- selective scan: block per (b,h,state-half), warp per 2 p ----------------
__global__ void __launch_bounds__(1024) scan_kernel(
    const float* __restrict__ xbc, const float* __restrict__ dtv,
    const float* __restrict__ A_log, const float* __restrict__ Dv,
    float* __restrict__ ya, float* __restrict__ yb2) {
    int sh = blockIdx.x & 1;          // state half
    int bh = blockIdx.x >> 1;
    int b = bh / NH;
    int hh = bh % NH;
    int warp = threadIdx.x >> 5, lane = threadIdx.x & 31;
    int p0 = warp, p1 = warp + 32;
    float A = -__expf(A_log[hh]);
    float Dh = Dv[hh];
    float h0 = 0.f, h1 = 0.f;
    const float* xb = xbc + (size_t)b * SEQL * CONVD;
    const float* dtp = dtv + (size_t)b * SEQL * NH + hh;
    float* yp = (sh == 0 ? ya : yb2) + (size_t)b * SEQL * DI + hh * HD;
    int soff = DI + sh * 32 + lane;
    for (int t = 0; t < SEQL; t++) {
        const float* row = xb + (size_t)t * CONVD;
        float dt = __ldg(dtp + (size_t)t * NH);
        float dA = __expf(dt * A);
        float Bn = __ldg(row + soff);
        float Cn = __ldg(row + soff + DS);
        float x0 = __ldg(row + hh * HD + p0);
        float x1 = __ldg(row + hh * HD + p1);
        h0 = fmaf(h0, dA, dt * x0 * Bn);
        h1 = fmaf(h1, dA, dt * x1 * Bn);
        float y0 = h0 * Cn;
        float y1 = h1 * Cn;
        #pragma unroll
        for (int o = 16; o; o >>= 1) {
            y0 += __shfl_xor_sync(0xffffffffu, y0, o);
            y1 += __shfl_xor_sync(0xffffffffu, y1, o);
        }
        if (lane == 0) {
            if (sh == 0) {
                yp[(size_t)t * DI + p0] = y0 + Dh * x0;
                yp[(size_t)t * DI + p1] = y1 + Dh * x1;
            } else {
                yp[(size_t)t * DI + p0] = y0;
                yp[(size_t)t * DI + p1] = y1;
            }
        }
    }
}

// ---------------- gated RMSNorm over DI=2048 (sums the two scan partials) ----------------
__global__ void rms_gate_kernel(const float* __restrict__ ya, const float* __restrict__ yb2,
                                const float* __restrict__ zx,
                                const float* __restrict__ nw, float* __restrict__ out) {
    __shared__ float smem[32];
    int row = blockIdx.x;
    float v[8];
    float s = 0.f;
    #pragma unroll
    for (int i = 0; i < 8; i++) {
        int c = threadIdx.x + i * 256;
        float z = zx[(size_t)row * DIP + c];
        float g = z * (1.f / (1.f + __expf(-z)));
        float vv = (ya[(size_t)row * DI + c] + yb2[(size_t)row * DI + c]) * g;
        v[i] = vv;
        s += vv * vv;
    }
    float ms = block_reduce_sum(s, smem) * (1.f / DI);
    float rs = rsqrtf(ms + EPSV);
    #pragma unroll
    for (int i = 0; i < 8; i++) {
        int c = threadIdx.x + i * 256;
        out[(size_t)row * DI + c] = v[i] * rs * nw[c];
    }
}

// ---------------- launch ----------------
extern "C" void kernel_launch(void* const* d_in, const int* in_sizes, int n_in,
                              void* d_out, int out_size) {
    const float* x        = (const float*)d_in[0];
    const float* ln1_w    = (const float*)d_in[1];
    const float* ln1_b    = (const float*)d_in[2];
    const float* in_proj  = (const float*)d_in[3];
    const float* conv_w   = (const float*)d_in[4];
    const float* conv_b   = (const float*)d_in[5];
    const float* dt_bias  = (const float*)d_in[6];
    const float* A_log    = (const float*)d_in[7];
    const float* Dv       = (const float*)d_in[8];
    const float* norm_w   = (const float*)d_in[9];
    const float* out_proj = (const float*)d_in[10];
    const float* ln2_w    = (const float*)d_in[11];
    const float* ln2_b    = (const float*)d_in[12];
    const float* mlp_w1   = (const float*)d_in[13];
    const float* mlp_b1   = (const float*)d_in[14];
    const float* mlp_w2   = (const float*)d_in[15];
    const float* mlp_b2   = (const float*)d_in[16];
    float* out = (float*)d_out;

    float *p_ln1, *p_zx, *p_xbc, *p_dt, *p_y, *p_y2, *p_yn, *p_x1, *p_h2, *p_mid;
    cudaGetSymbolAddress((void**)&p_ln1, g_ln1);
    cudaGetSymbolAddress((void**)&p_zx, g_zx);
    cudaGetSymbolAddress((void**)&p_xbc, g_xbc);
    cudaGetSymbolAddress((void**)&p_dt, g_dt);
    cudaGetSymbolAddress((void**)&p_y, g_y);
    cudaGetSymbolAddress((void**)&p_y2, g_y2);
    cudaGetSymbolAddress((void**)&p_yn, g_yn);
    cudaGetSymbolAddress((void**)&p_x1, g_x1);
    cudaGetSymbolAddress((void**)&p_h2, g_h2);
    cudaGetSymbolAddress((void**)&p_mid, g_mid);

    // 1. LN1
    ln_kernel<<<TOK, 256>>>(x, ln1_w, ln1_b, p_ln1);
    // 2. in_proj: [4096,1024] @ [4256,1024]^T -> [4096,4256]
    gemm_tc_kernel<<<dim3((DIP + 127) / 128, TOK / 128), 256>>>(
        p_ln1, in_proj, p_zx, TOK, DIP, DM, nullptr, nullptr, 0);
    // 3. conv + silu
    {
        int total = TOK * CONVD;
        conv_silu_kernel<<<(total + 255) / 256, 256>>>(p_zx, conv_w, conv_b, p_xbc);
    }
    // 4. dt
    dt_kernel<<<(TOK * NH + 255) / 256, 256>>>(p_zx, dt_bias, p_dt);
    // 5. selective scan (state-split over 128 blocks)
    scan_kernel<<<BATCH * NH * 2, 1024>>>(p_xbc, p_dt, A_log, Dv, p_y, p_y2);
    // 6. gated rmsnorm (sums partials)
    rms_gate_kernel<<<TOK, 256>>>(p_y, p_y2, p_zx, norm_w, p_yn);
    // 7. out_proj + residual(x) -> x1
    gemm_tc_kernel<<<dim3(DM / 128, TOK / 128), 256>>>(
        p_yn, out_proj, p_x1, TOK, DM, DI, nullptr, x, 0);
    // 8. LN2
    ln_kernel<<<TOK, 256>>>(p_x1, ln2_w, ln2_b, p_h2);
    // 9. MLP1 + bias + gelu
    gemm_tc_kernel<<<dim3(DMLP / 128, TOK / 128), 256>>>(
        p_h2, mlp_w1, p_mid, TOK, DMLP, DM, mlp_b1, nullptr, 1);
    // 10. MLP2 + bias + residual(x1) -> out
    gemm_tc_kernel<<<dim3(DM / 128, TOK / 128), 256>>>(
        p_mid, mlp_w2, out, TOK, DM, DMLP, mlp_b2, p_x1, 0);
}

// round 15
// speedup vs baseline: 3.0131x; 1.1440x over previous
#include <cuda_runtime.h>
#include <cuda_bf16.h>
#include <math.h>
#include <stdint.h>

// ---------------- problem constants ----------------
#define BATCH 2
#define SEQL 2048
#define TOK (BATCH * SEQL)          // 4096
#define DM 1024
#define DI 2048
#define NH 32
#define HD 64
#define DS 64
#define DCONV 4
#define CONVD (DI + 2 * DS)         // 2176
#define DIP (2 * DI + 2 * DS + NH)  // 4256
#define DMLP (4 * DM)               // 4096
#define EPSV 1e-5f

// ---------------- scratch (allocation-free) ----------------
__device__ float g_ln1[TOK * DM];
__device__ float g_zx[TOK * DIP];
__device__ float g_xbc[TOK * CONVD];
__device__ float g_dt[TOK * NH];
__device__ float g_y[TOK * DI];
__device__ float g_y2[TOK * DI];
__device__ float g_yn[TOK * DI];
__device__ float g_x1[TOK * DM];
__device__ float g_h2[TOK * DM];
__device__ float g_mid[TOK * DMLP];
// tf32-rounded weight copies
__device__ float g_wip[DIP * DM];
__device__ float g_wop[DM * DI];
__device__ float g_w1[DMLP * DM];
__device__ float g_w2[DM * DMLP];

// ---------------- helpers ----------------
__device__ __forceinline__ uint32_t smem_to_u32(const void* p) {
    uint32_t a;
    asm("{ .reg .u64 t; cvta.to.shared.u64 t, %1; cvt.u32.u64 %0, t; }"
        : "=r"(a) : "l"(p));
    return a;
}
__device__ __forceinline__ uint32_t f2tf(float f) {
    uint32_t u;
    asm("cvt.rna.tf32.f32 %0, %1;" : "=r"(u) : "f"(f));
    return u;
}
__device__ __forceinline__ float roundtf(float f) { return __uint_as_float(f2tf(f)); }

__device__ __forceinline__ void mma_tf32(float* c, uint32_t a0, uint32_t a1,
                                         uint32_t a2, uint32_t a3,
                                         uint32_t b0, uint32_t b1) {
    asm volatile(
        "mma.sync.aligned.m16n8k8.row.col.f32.tf32.tf32.f32 "
        "{%0,%1,%2,%3}, {%4,%5,%6,%7}, {%8,%9}, {%0,%1,%2,%3};"
        : "+f"(c[0]), "+f"(c[1]), "+f"(c[2]), "+f"(c[3])
        : "r"(a0), "r"(a1), "r"(a2), "r"(a3), "r"(b0), "r"(b1));
}

__device__ __forceinline__ float block_reduce_sum(float v, float* smem) {
    int lane = threadIdx.x & 31, wid = threadIdx.x >> 5;
    #pragma unroll
    for (int o = 16; o; o >>= 1) v += __shfl_xor_sync(0xffffffffu, v, o);
    if (lane == 0) smem[wid] = v;
    __syncthreads();
    float r = (threadIdx.x < (blockDim.x >> 5)) ? smem[threadIdx.x] : 0.f;
    if (wid == 0) {
        #pragma unroll
        for (int o = 16; o; o >>= 1) r += __shfl_xor_sync(0xffffffffu, r, o);
        if (lane == 0) smem[0] = r;
    }
    __syncthreads();
    r = smem[0];
    __syncthreads();
    return r;
}

// ---------------- tf32 pre-round (weights) ----------------
__global__ void round_tf32_kernel(const float* __restrict__ in, float* __restrict__ out, int n4) {
    int i = blockIdx.x * blockDim.x + threadIdx.x;
    if (i >= n4) return;
    float4 v = reinterpret_cast<const float4*>(in)[i];
    uint4 u;
    u.x = f2tf(v.x); u.y = f2tf(v.y); u.z = f2tf(v.z); u.w = f2tf(v.w);
    reinterpret_cast<uint4*>(out)[i] = u;
}

// ---------------- LayerNorm over DM=1024 (tf32-rounded output: feeds GEMM) ----------------
__global__ void ln_kernel(const float* __restrict__ x, const float* __restrict__ w,
                          const float* __restrict__ b, float* __restrict__ out) {
    __shared__ float smem[32];
    int row = blockIdx.x;
    const float* xr = x + (size_t)row * DM;
    float v[4];
    float s = 0.f;
    #pragma unroll
    for (int i = 0; i < 4; i++) { v[i] = xr[threadIdx.x + i * 256]; s += v[i]; }
    float mean = block_reduce_sum(s, smem) * (1.f / DM);
    float s2 = 0.f;
    #pragma unroll
    for (int i = 0; i < 4; i++) { float d = v[i] - mean; s2 += d * d; }
    float var = block_reduce_sum(s2, smem) * (1.f / DM);
    float rs = rsqrtf(var + EPSV);
    #pragma unroll
    for (int i = 0; i < 4; i++) {
        int c = threadIdx.x + i * 256;
        out[(size_t)row * DM + c] = roundtf((v[i] - mean) * rs * w[c] + b[c]);
    }
}

// ---------------- Tensor-core tf32 GEMM, cp.async 3-stage pipeline ----------------
// C[M,N] = A[M,K] @ W[N,K]^T, operands pre-rounded tf32-exact fp32.
// CTA tile 128x128, 256 threads = 8 warps (4x2), warp tile 32x64, K-chunk 32.
// Smem stage = A[128x32] + B[128x32] fp32, XOR-swizzled at 16B granularity
// (element col = k ^ (4*(row&7)) — identical fragment addressing to the
// round-8 kernel). 3 stages in a ring, cp.async prefetch distance 2.
#define STAGES 3
#define STAGE_U32 (2 * 4096)                    // A 4096 + B 4096 u32
#define GEMM_SMEM_BYTES (STAGES * STAGE_U32 * 4)  // 98304
__global__ void __launch_bounds__(256, 2) gemm_tc_kernel(
    const float* __restrict__ A, const float* __restrict__ W, float* __restrict__ C,
    int M, int N, int K,
    const float* __restrict__ bias, const float* __restrict__ res, int act) {
    extern __shared__ uint32_t sm[];
    const uint32_t smem_u32 = smem_to_u32(sm);
    const int tid = threadIdx.x;
    const int lane = tid & 31;
    const int warp = tid >> 5;
    const int g = lane >> 2;   // 0..7
    const int t = lane & 3;    // 0..3
    const int wm = warp >> 1;  // 0..3
    const int wn = warp & 1;   // 0..1
    const int m0 = blockIdx.y * 128;
    const int n0 = blockIdx.x * 128;
    const int nk = K / 32;

    // issue one stage's loads (A: 4 quads/thread, B: 4 quads/thread) + commit
    auto issue_stage = [&](int s, int k0) {
        const uint32_t sa = smem_u32 + (uint32_t)(s * STAGE_U32 * 4);
        const uint32_t sb = sa + 16384;
        #pragma unroll
        for (int i = 0; i < 4; i++) {
            int lin = tid + 256 * i;
            int r = lin >> 3, q = lin & 7;
            uint32_t off = (uint32_t)(r * 128 + ((16 * q) ^ (16 * (r & 7))));
            const float* src = &A[(size_t)(m0 + r) * K + k0 + q * 4];
            asm volatile("cp.async.cg.shared.global [%0], [%1], 16;"
                         :: "r"(sa + off), "l"(src));
        }
        #pragma unroll
        for (int i = 0; i < 4; i++) {
            int lin = tid + 256 * i;
            int r = lin >> 3, q = lin & 7;
            int n = n0 + r;
            uint32_t off = (uint32_t)(r * 128 + ((16 * q) ^ (16 * (r & 7))));
            const float* src = &W[(size_t)(n < N ? n : 0) * K + k0 + q * 4];
            uint32_t ss = (n < N) ? 16u : 0u;  // zero-fill beyond N
            asm volatile("cp.async.cg.shared.global [%0], [%1], 16, %2;"
                         :: "r"(sb + off), "l"(src), "r"(ss));
        }
        asm volatile("cp.async.commit_group;" ::: "memory");
    };

    float c[2][8][4] = {};

    // prologue: stages 0 and 1 in flight
    issue_stage(0, 0);
    issue_stage(1, 32);

    const uint32_t xg = 4 * (uint32_t)g;
    for (int ck = 0; ck < nk; ck++) {
        // keep group numbering uniform: one commit per iteration
        if (ck + 2 < nk) issue_stage((ck + 2) % STAGES, (ck + 2) * 32);
        else asm volatile("cp.async.commit_group;" ::: "memory");
        // wait until stage ck's group is complete (<=2 newer groups pending)
        asm volatile("cp.async.wait_group 2;" ::: "memory");
        __syncthreads();

        const uint32_t* as = sm + (ck % STAGES) * STAGE_U32;
        const uint32_t* bs = as + 4096;
        #pragma unroll
        for (int ks = 0; ks < 4; ks++) {
            const uint32_t kk = (uint32_t)(ks * 8 + t);
            uint32_t bf[8][2];
            #pragma unroll
            for (int jt = 0; jt < 8; jt++) {
                int colr = wn * 64 + jt * 8 + g;
                bf[jt][0] = bs[colr * 32 + (kk ^ xg)];
                bf[jt][1] = bs[colr * 32 + ((kk + 4) ^ xg)];
            }
            #pragma unroll
            for (int it = 0; it < 2; it++) {
                int r0 = wm * 32 + it * 16 + g;
                int r1 = r0 + 8;
                uint32_t a0 = as[r0 * 32 + (kk ^ xg)];
                uint32_t a1 = as[r1 * 32 + (kk ^ xg)];
                uint32_t a2 = as[r0 * 32 + ((kk + 4) ^ xg)];
                uint32_t a3 = as[r1 * 32 + ((kk + 4) ^ xg)];
                #pragma unroll
                for (int jt = 0; jt < 8; jt++)
                    mma_tf32(c[it][jt], a0, a1, a2, a3, bf[jt][0], bf[jt][1]);
            }
        }
        // stage ck is dead after this barrier; next iteration may overwrite it
        __syncthreads();
    }

    // ---- epilogue ----
    #pragma unroll
    for (int it = 0; it < 2; it++) {
        int r0 = m0 + wm * 32 + it * 16 + g;
        int r1 = r0 + 8;
        #pragma unroll
        for (int jt = 0; jt < 8; jt++) {
            int nn = n0 + wn * 64 + jt * 8 + 2 * t;
            if (nn < N) {
                float v[4] = {c[it][jt][0], c[it][jt][1], c[it][jt][2], c[it][jt][3]};
                if (bias) {
                    float b0 = bias[nn], b1 = bias[nn + 1];
                    v[0] += b0; v[1] += b1; v[2] += b0; v[3] += b1;
                }
                if (act == 1) {
                    #pragma unroll
                    for (int q = 0; q < 4; q++) {
                        v[q] = 0.5f * v[q] * (1.f + erff(v[q] * 0.70710678118654752f));
                        v[q] = roundtf(v[q]);  // feeds next GEMM via cp.async
                    }
                }
                if (res) {
                    v[0] += res[(size_t)r0 * N + nn];
                    v[1] += res[(size_t)r0 * N + nn + 1];
                    v[2] += res[(size_t)r1 * N + nn];
                    v[3] += res[(size_t)r1 * N + nn + 1];
                }
                *reinterpret_cast<float2*>(&C[(size_t)r0 * N + nn]) = make_float2(v[0], v[1]);
                *reinterpret_cast<float2*>(&C[(size_t)r1 * N + nn]) = make_float2(v[2], v[3]);
            }
        }
    }
}

// ---------------- depthwise causal conv + silu on xBC ----------------
__global__ void conv_silu_kernel(const float* __restrict__ zx, const float* __restrict__ cw,
                                 const float* __restrict__ cb, float* __restrict__ out) {
    int idx = blockIdx.x * blockDim.x + threadIdx.x;
    if (idx >= TOK * CONVD) return;
    int c = idx % CONVD;
    int t = idx / CONVD;
    int b = t / SEQL, l = t % SEQL;
    float acc = cb[c];
    #pragma unroll
    for (int k = 0; k < DCONV; k++) {
        int lk = l - (DCONV - 1) + k;
        if (lk >= 0)
            acc = fmaf(zx[((size_t)(b * SEQL + lk)) * DIP + DI + c], cw[c * DCONV + k], acc);
    }
    out[idx] = acc * (1.f / (1.f + __expf(-acc)));
}

// ---------------- dt = softplus(raw + dt_bias) ----------------
__global__ void dt_kernel(const float* __restrict__ zx, const float* __restrict__ dtb,
                          float* __restrict__ dt) {
    int idx = blockIdx.x * blockDim.x + threadIdx.x;
    if (idx >= TOK * NH) return;
    int h = idx % NH;
    float v = zx[(size_t)(idx / NH) * DIP + DI + CONVD + h] + dtb[h];
    dt[idx] = (v > 20.f) ? v : log1pf(expf(v));
}

// ---------------- selective scan: block per (b,h,state-half), warp per 2 p ----------------
__global__ void __launch_bounds__(1024) scan_kernel(
    const float* __restrict__ xbc, const float* __restrict__ dtv,
    const float* __restrict__ A_log, const float* __restrict__ Dv,
    float* __restrict__ ya, float* __restrict__ yb2) {
    int sh = blockIdx.x & 1;
    int bh = blockIdx.x >> 1;
    int b = bh / NH;
    int hh = bh % NH;
    int warp = threadIdx.x >> 5, lane = threadIdx.x & 31;
    int p0 = warp, p1 = warp + 32;
    float A = -__expf(A_log[hh]);
    float Dh = Dv[hh];
    float h0 = 0.f, h1 = 0.f;
    const float* xb = xbc + (size_t)b * SEQL * CONVD;
    const float* dtp = dtv + (size_t)b * SEQL * NH + hh;
    float* yp = (sh == 0 ? ya : yb2) + (size_t)b * SEQL * DI + hh * HD;
    int soff = DI + sh * 32 + lane;
    for (int t = 0; t < SEQL; t++) {
        const float* row = xb + (size_t)t * CONVD;
        float dt = __ldg(dtp + (size_t)t * NH);
        float dA = __expf(dt * A);
        float Bn = __ldg(row + soff);
        float Cn = __ldg(row + soff + DS);
        float x0 = __ldg(row + hh * HD + p0);
        float x1 = __ldg(row + hh * HD + p1);
        h0 = fmaf(h0, dA, dt * x0 * Bn);
        h1 = fmaf(h1, dA, dt * x1 * Bn);
        float y0 = h0 * Cn;
        float y1 = h1 * Cn;
        #pragma unroll
        for (int o = 16; o; o >>= 1) {
            y0 += __shfl_xor_sync(0xffffffffu, y0, o);
            y1 += __shfl_xor_sync(0xffffffffu, y1, o);
        }
        if (lane == 0) {
            if (sh == 0) {
                yp[(size_t)t * DI + p0] = y0 + Dh * x0;
                yp[(size_t)t * DI + p1] = y1 + Dh * x1;
            } else {
                yp[(size_t)t * DI + p0] = y0;
                yp[(size_t)t * DI + p1] = y1;
            }
        }
    }
}

// ---------------- gated RMSNorm over DI=2048 (tf32-rounded output: feeds GEMM) ----------------
__global__ void rms_gate_kernel(const float* __restrict__ ya, const float* __restrict__ yb2,
                                const float* __restrict__ zx,
                                const float* __restrict__ nw, float* __restrict__ out) {
    __shared__ float smem[32];
    int row = blockIdx.x;
    float v[8];
    float s = 0.f;
    #pragma unroll
    for (int i = 0; i < 8; i++) {
        int c = threadIdx.x + i * 256;
        float z = zx[(size_t)row * DIP + c];
        float g = z * (1.f / (1.f + __expf(-z)));
        float vv = (ya[(size_t)row * DI + c] + yb2[(size_t)row * DI + c]) * g;
        v[i] = vv;
        s += vv * vv;
    }
    float ms = block_reduce_sum(s, smem) * (1.f / DI);
    float rs = rsqrtf(ms + EPSV);
    #pragma unroll
    for (int i = 0; i < 8; i++) {
        int c = threadIdx.x + i * 256;
        out[(size_t)row * DI + c] = roundtf(v[i] * rs * nw[c]);
    }
}

// ---------------- launch ----------------
extern "C" void kernel_launch(void* const* d_in, const int* in_sizes, int n_in,
                              void* d_out, int out_size) {
    const float* x        = (const float*)d_in[0];
    const float* ln1_w    = (const float*)d_in[1];
    const float* ln1_b    = (const float*)d_in[2];
    const float* in_proj  = (const float*)d_in[3];
    const float* conv_w   = (const float*)d_in[4];
    const float* conv_b   = (const float*)d_in[5];
    const float* dt_bias  = (const float*)d_in[6];
    const float* A_log    = (const float*)d_in[7];
    const float* Dv       = (const float*)d_in[8];
    const float* norm_w   = (const float*)d_in[9];
    const float* out_proj = (const float*)d_in[10];
    const float* ln2_w    = (const float*)d_in[11];
    const float* ln2_b    = (const float*)d_in[12];
    const float* mlp_w1   = (const float*)d_in[13];
    const float* mlp_b1   = (const float*)d_in[14];
    const float* mlp_w2   = (const float*)d_in[15];
    const float* mlp_b2   = (const float*)d_in[16];
    float* out = (float*)d_out;

    float *p_ln1, *p_zx, *p_xbc, *p_dt, *p_y, *p_y2, *p_yn, *p_x1, *p_h2, *p_mid;
    float *p_wip, *p_wop, *p_w1, *p_w2;
    cudaGetSymbolAddress((void**)&p_ln1, g_ln1);
    cudaGetSymbolAddress((void**)&p_zx, g_zx);
    cudaGetSymbolAddress((void**)&p_xbc, g_xbc);
    cudaGetSymbolAddress((void**)&p_dt, g_dt);
    cudaGetSymbolAddress((void**)&p_y, g_y);
    cudaGetSymbolAddress((void**)&p_y2, g_y2);
    cudaGetSymbolAddress((void**)&p_yn, g_yn);
    cudaGetSymbolAddress((void**)&p_x1, g_x1);
    cudaGetSymbolAddress((void**)&p_h2, g_h2);
    cudaGetSymbolAddress((void**)&p_mid, g_mid);
    cudaGetSymbolAddress((void**)&p_wip, g_wip);
    cudaGetSymbolAddress((void**)&p_wop, g_wop);
    cudaGetSymbolAddress((void**)&p_w1, g_w1);
    cudaGetSymbolAddress((void**)&p_w2, g_w2);

    cudaFuncSetAttribute(gemm_tc_kernel,
                         cudaFuncAttributeMaxDynamicSharedMemorySize, GEMM_SMEM_BYTES);

    // 0. pre-round weights to tf32-exact fp32
    {
        int n4;
        n4 = DIP * DM / 4;  round_tf32_kernel<<<(n4 + 255) / 256, 256>>>(in_proj, p_wip, n4);
        n4 = DM * DI / 4;   round_tf32_kernel<<<(n4 + 255) / 256, 256>>>(out_proj, p_wop, n4);
        n4 = DMLP * DM / 4; round_tf32_kernel<<<(n4 + 255) / 256, 256>>>(mlp_w1, p_w1, n4);
        n4 = DM * DMLP / 4; round_tf32_kernel<<<(n4 + 255) / 256, 256>>>(mlp_w2, p_w2, n4);
    }
    // 1. LN1 (rounded output)
    ln_kernel<<<TOK, 256>>>(x, ln1_w, ln1_b, p_ln1);
    // 2. in_proj: [4096,1024] @ [4256,1024]^T -> [4096,4256]
    gemm_tc_kernel<<<dim3((DIP + 127) / 128, TOK / 128), 256, GEMM_SMEM_BYTES>>>(
        p_ln1, p_wip, p_zx, TOK, DIP, DM, nullptr, nullptr, 0);
    // 3. conv + silu
    {
        int total = TOK * CONVD;
        conv_silu_kernel<<<(total + 255) / 256, 256>>>(p_zx, conv_w, conv_b, p_xbc);
    }
    // 4. dt
    dt_kernel<<<(TOK * NH + 255) / 256, 256>>>(p_zx, dt_bias, p_dt);
    // 5. selective scan (state-split, 128 blocks)
    scan_kernel<<<BATCH * NH * 2, 1024>>>(p_xbc, p_dt, A_log, Dv, p_y, p_y2);
    // 6. gated rmsnorm (rounded output)
    rms_gate_kernel<<<TOK, 256>>>(p_y, p_y2, p_zx, norm_w, p_yn);
    // 7. out_proj + residual(x) -> x1
    gemm_tc_kernel<<<dim3(DM / 128, TOK / 128), 256, GEMM_SMEM_BYTES>>>(
        p_yn, p_wop, p_x1, TOK, DM, DI, nullptr, x, 0);
    // 8. LN2 (rounded output)
    ln_kernel<<<TOK, 256>>>(p_x1, ln2_w, ln2_b, p_h2);
    // 9. MLP1 + bias + gelu (rounded output)
    gemm_tc_kernel<<<dim3(DMLP / 128, TOK / 128), 256, GEMM_SMEM_BYTES>>>(
        p_h2, p_w1, p_mid, TOK, DMLP, DM, mlp_b1, nullptr, 1);
    // 10. MLP2 + bias + residual(x1) -> out
    gemm_tc_kernel<<<dim3(DM / 128, TOK / 128), 256, GEMM_SMEM_BYTES>>>(
        p_mid, p_w2, out, TOK, DM, DMLP, mlp_b2, p_x1, 0);
}

// round 17
// speedup vs baseline: 3.0931x; 1.0266x over previous
#include <cuda_runtime.h>
#include <cuda_bf16.h>
#include <math.h>
#include <stdint.h>

// ---------------- problem constants ----------------
#define BATCH 2
#define SEQL 2048
#define TOK (BATCH * SEQL)          // 4096
#define DM 1024
#define DI 2048
#define NH 32
#define HD 64
#define DS 64
#define DCONV 4
#define CONVD (DI + 2 * DS)         // 2176
#define DIP (2 * DI + 2 * DS + NH)  // 4256
#define DMLP (4 * DM)               // 4096
#define EPSV 1e-5f

// ---------------- scratch (allocation-free) ----------------
__device__ float g_ln1[TOK * DM];
__device__ float g_zx[TOK * DIP];
__device__ float g_xbc[TOK * CONVD];
__device__ float g_dt[TOK * NH];
__device__ float g_ya[TOK * DI];   // scan partial, n 0..15 (+ D*x)
__device__ float g_yb[TOK * DI];   // n 16..31
__device__ float g_yc[TOK * DI];   // n 32..47
__device__ float g_yd[TOK * DI];   // n 48..63
__device__ float g_yn[TOK * DI];
__device__ float g_x1[TOK * DM];
__device__ float g_h2[TOK * DM];
__device__ float g_mid[TOK * DMLP];
// tf32-rounded weight copies
__device__ float g_wip[DIP * DM];
__device__ float g_wop[DM * DI];
__device__ float g_w1[DMLP * DM];
__device__ float g_w2[DM * DMLP];

// ---------------- helpers ----------------
__device__ __forceinline__ uint32_t smem_to_u32(const void* p) {
    uint32_t a;
    asm("{ .reg .u64 t; cvta.to.shared.u64 t, %1; cvt.u32.u64 %0, t; }"
        : "=r"(a) : "l"(p));
    return a;
}
__device__ __forceinline__ uint32_t f2tf(float f) {
    uint32_t u;
    asm("cvt.rna.tf32.f32 %0, %1;" : "=r"(u) : "f"(f));
    return u;
}
__device__ __forceinline__ float roundtf(float f) { return __uint_as_float(f2tf(f)); }

__device__ __forceinline__ void mma_tf32(float* c, uint32_t a0, uint32_t a1,
                                         uint32_t a2, uint32_t a3,
                                         uint32_t b0, uint32_t b1) {
    asm volatile(
        "mma.sync.aligned.m16n8k8.row.col.f32.tf32.tf32.f32 "
        "{%0,%1,%2,%3}, {%4,%5,%6,%7}, {%8,%9}, {%0,%1,%2,%3};"
        : "+f"(c[0]), "+f"(c[1]), "+f"(c[2]), "+f"(c[3])
        : "r"(a0), "r"(a1), "r"(a2), "r"(a3), "r"(b0), "r"(b1));
}

__device__ __forceinline__ float block_reduce_sum(float v, float* smem) {
    int lane = threadIdx.x & 31, wid = threadIdx.x >> 5;
    #pragma unroll
    for (int o = 16; o; o >>= 1) v += __shfl_xor_sync(0xffffffffu, v, o);
    if (lane == 0) smem[wid] = v;
    __syncthreads();
    float r = (threadIdx.x < (blockDim.x >> 5)) ? smem[threadIdx.x] : 0.f;
    if (wid == 0) {
        #pragma unroll
        for (int o = 16; o; o >>= 1) r += __shfl_xor_sync(0xffffffffu, r, o);
        if (lane == 0) smem[0] = r;
    }
    __syncthreads();
    r = smem[0];
    __syncthreads();
    return r;
}

// ---------------- tf32 pre-round (weights) ----------------
__global__ void round_tf32_kernel(const float* __restrict__ in, float* __restrict__ out, int n4) {
    int i = blockIdx.x * blockDim.x + threadIdx.x;
    if (i >= n4) return;
    float4 v = reinterpret_cast<const float4*>(in)[i];
    uint4 u;
    u.x = f2tf(v.x); u.y = f2tf(v.y); u.z = f2tf(v.z); u.w = f2tf(v.w);
    reinterpret_cast<uint4*>(out)[i] = u;
}

// ---------------- LayerNorm over DM=1024 (tf32-rounded output: feeds GEMM) ----------------
__global__ void ln_kernel(const float* __restrict__ x, const float* __restrict__ w,
                          const float* __restrict__ b, float* __restrict__ out) {
    __shared__ float smem[32];
    int row = blockIdx.x;
    const float* xr = x + (size_t)row * DM;
    float v[4];
    float s = 0.f;
    #pragma unroll
    for (int i = 0; i < 4; i++) { v[i] = xr[threadIdx.x + i * 256]; s += v[i]; }
    float mean = block_reduce_sum(s, smem) * (1.f / DM);
    float s2 = 0.f;
    #pragma unroll
    for (int i = 0; i < 4; i++) { float d = v[i] - mean; s2 += d * d; }
    float var = block_reduce_sum(s2, smem) * (1.f / DM);
    float rs = rsqrtf(var + EPSV);
    #pragma unroll
    for (int i = 0; i < 4; i++) {
        int c = threadIdx.x + i * 256;
        out[(size_t)row * DM + c] = roundtf((v[i] - mean) * rs * w[c] + b[c]);
    }
}

// ---------------- Tensor-core tf32 GEMM, cp.async 3-stage, 1 barrier/chunk ----------------
// C[M,N] = A[M,K] @ W[N,K]^T, operands pre-rounded tf32-exact fp32.
// CTA tile 128x128, 256 threads = 8 warps (4x2), warp tile 32x64, K-chunk 32.
// Loop: wait_group 1 -> sync -> issue(ck+2) -> compute(ck). Stage (ck+2)%3 was
// last read at iter ck-1, whose completion the barrier guarantees. Uniform empty
// commits keep group numbering exact at the tail.
#define STAGES 3
#define STAGE_U32 (2 * 4096)                    // A 4096 + B 4096 u32
#define GEMM_SMEM_BYTES (STAGES * STAGE_U32 * 4)  // 98304
__global__ void __launch_bounds__(256, 2) gemm_tc_kernel(
    const float* __restrict__ A, const float* __restrict__ W, float* __restrict__ C,
    int M, int N, int K,
    const float* __restrict__ bias, const float* __restrict__ res, int act) {
    extern __shared__ uint32_t sm[];
    const uint32_t smem_u32 = smem_to_u32(sm);
    const int tid = threadIdx.x;
    const int lane = tid & 31;
    const int warp = tid >> 5;
    const int g = lane >> 2;   // 0..7
    const int t = lane & 3;    // 0..3
    const int wm = warp >> 1;  // 0..3
    const int wn = warp & 1;   // 0..1
    const int m0 = blockIdx.y * 128;
    const int n0 = blockIdx.x * 128;
    const int nk = K / 32;

    auto issue_stage = [&](int s, int k0) {
        const uint32_t sa = smem_u32 + (uint32_t)(s * STAGE_U32 * 4);
        const uint32_t sb = sa + 16384;
        #pragma unroll
        for (int i = 0; i < 4; i++) {
            int lin = tid + 256 * i;
            int r = lin >> 3, q = lin & 7;
            uint32_t off = (uint32_t)(r * 128 + ((16 * q) ^ (16 * (r & 7))));
            const float* src = &A[(size_t)(m0 + r) * K + k0 + q * 4];
            asm volatile("cp.async.cg.shared.global [%0], [%1], 16;"
                         :: "r"(sa + off), "l"(src));
        }
        #pragma unroll
        for (int i = 0; i < 4; i++) {
            int lin = tid + 256 * i;
            int r = lin >> 3, q = lin & 7;
            int n = n0 + r;
            uint32_t off = (uint32_t)(r * 128 + ((16 * q) ^ (16 * (r & 7))));
            const float* src = &W[(size_t)(n < N ? n : 0) * K + k0 + q * 4];
            uint32_t ss = (n < N) ? 16u : 0u;
            asm volatile("cp.async.cg.shared.global [%0], [%1], 16, %2;"
                         :: "r"(sb + off), "l"(src), "r"(ss));
        }
        asm volatile("cp.async.commit_group;" ::: "memory");
    };

    float c[2][8][4] = {};

    issue_stage(0, 0);
    issue_stage(1, 32);

    const uint32_t xg = 4 * (uint32_t)g;
    for (int ck = 0; ck < nk; ck++) {
        // groups committed so far: ck+2 (0..ck+1). Allow 1 pending => group ck done.
        asm volatile("cp.async.wait_group 1;" ::: "memory");
        __syncthreads();
        if (ck + 2 < nk) issue_stage((ck + 2) % STAGES, (ck + 2) * 32);
        else asm volatile("cp.async.commit_group;" ::: "memory");

        const uint32_t* as = sm + (ck % STAGES) * STAGE_U32;
        const uint32_t* bs = as + 4096;
        #pragma unroll
        for (int ks = 0; ks < 4; ks++) {
            const uint32_t kk = (uint32_t)(ks * 8 + t);
            uint32_t bf[8][2];
            #pragma unroll
            for (int jt = 0; jt < 8; jt++) {
                int colr = wn * 64 + jt * 8 + g;
                bf[jt][0] = bs[colr * 32 + (kk ^ xg)];
                bf[jt][1] = bs[colr * 32 + ((kk + 4) ^ xg)];
            }
            #pragma unroll
            for (int it = 0; it < 2; it++) {
                int r0 = wm * 32 + it * 16 + g;
                int r1 = r0 + 8;
                uint32_t a0 = as[r0 * 32 + (kk ^ xg)];
                uint32_t a1 = as[r1 * 32 + (kk ^ xg)];
                uint32_t a2 = as[r0 * 32 + ((kk + 4) ^ xg)];
                uint32_t a3 = as[r1 * 32 + ((kk + 4) ^ xg)];
                #pragma unroll
                for (int jt = 0; jt < 8; jt++)
                    mma_tf32(c[it][jt], a0, a1, a2, a3, bf[jt][0], bf[jt][1]);
            }
        }
    }

    // ---- epilogue ----
    #pragma unroll
    for (int it = 0; it < 2; it++) {
        int r0 = m0 + wm * 32 + it * 16 + g;
        int r1 = r0 + 8;
        #pragma unroll
        for (int jt = 0; jt < 8; jt++) {
            int nn = n0 + wn * 64 + jt * 8 + 2 * t;
            if (nn < N) {
                float v[4] = {c[it][jt][0], c[it][jt][1], c[it][jt][2], c[it][jt][3]};
                if (bias) {
                    float b0 = bias[nn], b1 = bias[nn + 1];
                    v[0] += b0; v[1] += b1; v[2] += b0; v[3] += b1;
                }
                if (act == 1) {
                    #pragma unroll
                    for (int q = 0; q < 4; q++) {
                        v[q] = 0.5f * v[q] * (1.f + erff(v[q] * 0.70710678118654752f));
                        v[q] = roundtf(v[q]);
                    }
                }
                if (res) {
                    v[0] += res[(size_t)r0 * N + nn];
                    v[1] += res[(size_t)r0 * N + nn + 1];
                    v[2] += res[(size_t)r1 * N + nn];
                    v[3] += res[(size_t)r1 * N + nn + 1];
                }
                *reinterpret_cast<float2*>(&C[(size_t)r0 * N + nn]) = make_float2(v[0], v[1]);
                *reinterpret_cast<float2*>(&C[(size_t)r1 * N + nn]) = make_float2(v[2], v[3]);
            }
        }
    }
}

// ---------------- depthwise causal conv + silu, float4 over channels ----------------
__global__ void conv_silu_kernel(const float* __restrict__ zx, const float* __restrict__ cw,
                                 const float* __restrict__ cb, float* __restrict__ out) {
    int idx = blockIdx.x * blockDim.x + threadIdx.x;     // over TOK*CONVD/4
    if (idx >= TOK * CONVD / 4) return;
    int c4 = (idx % (CONVD / 4)) * 4;
    int tok = idx / (CONVD / 4);
    int b = tok / SEQL, l = tok % SEQL;
    float4 acc = *reinterpret_cast<const float4*>(&cb[c4]);
    // per-channel weights: cw[c][k], k=0..3
    float4 w0 = *reinterpret_cast<const float4*>(&cw[(c4 + 0) * DCONV]);
    float4 w1 = *reinterpret_cast<const float4*>(&cw[(c4 + 1) * DCONV]);
    float4 w2 = *reinterpret_cast<const float4*>(&cw[(c4 + 2) * DCONV]);
    float4 w3 = *reinterpret_cast<const float4*>(&cw[(c4 + 3) * DCONV]);
    const float wk[4][4] = {{w0.x, w0.y, w0.z, w0.w}, {w1.x, w1.y, w1.z, w1.w},
                            {w2.x, w2.y, w2.z, w2.w}, {w3.x, w3.y, w3.z, w3.w}};
    float a[4] = {acc.x, acc.y, acc.z, acc.w};
    #pragma unroll
    for (int k = 0; k < DCONV; k++) {
        int lk = l - (DCONV - 1) + k;
        if (lk >= 0) {
            float4 xv = *reinterpret_cast<const float4*>(
                &zx[((size_t)(b * SEQL + lk)) * DIP + DI + c4]);
            a[0] = fmaf(xv.x, wk[0][k], a[0]);
            a[1] = fmaf(xv.y, wk[1][k], a[1]);
            a[2] = fmaf(xv.z, wk[2][k], a[2]);
            a[3] = fmaf(xv.w, wk[3][k], a[3]);
        }
    }
    float4 r;
    r.x = a[0] * (1.f / (1.f + __expf(-a[0])));
    r.y = a[1] * (1.f / (1.f + __expf(-a[1])));
    r.z = a[2] * (1.f / (1.f + __expf(-a[2])));
    r.w = a[3] * (1.f / (1.f + __expf(-a[3])));
    *reinterpret_cast<float4*>(&out[(size_t)tok * CONVD + c4]) = r;
}

// ---------------- dt = softplus(raw + dt_bias) ----------------
__global__ void dt_kernel(const float* __restrict__ zx, const float* __restrict__ dtb,
                          float* __restrict__ dt) {
    int idx = blockIdx.x * blockDim.x + threadIdx.x;
    if (idx >= TOK * NH) return;
    int h = idx % NH;
    float v = zx[(size_t)(idx / NH) * DIP + DI + CONVD + h] + dtb[h];
    dt[idx] = (v > 20.f) ? v : log1pf(expf(v));
}

// ---------------- selective scan: register-resident states, no shuffles ----------------
// 512 single-warp blocks: (b,h) x (p-half) x (n-quarter). lane = p within half.
// Each lane keeps h[16] (its n-quarter of the state for its p) in registers.
// y-partials per n-quarter go to 4 buffers, summed in rms_gate.
__global__ void __launch_bounds__(32) scan_kernel(
    const float* __restrict__ xbc, const float* __restrict__ dtv,
    const float* __restrict__ A_log, const float* __restrict__ Dv,
    float* __restrict__ ya, float* __restrict__ yb,
    float* __restrict__ yc, float* __restrict__ yd) {
    const int nq = blockIdx.x & 3;
    const int ph = (blockIdx.x >> 2) & 1;
    const int bh = blockIdx.x >> 3;
    const int b = bh >> 5, hh = bh & 31;
    const int lane = threadIdx.x;
    const int p = ph * 32 + lane;
    const float A = -__expf(A_log[hh]);
    const float Dh = Dv[hh];
    float h[16];
    #pragma unroll
    for (int j = 0; j < 16; j++) h[j] = 0.f;
    const float* xb = xbc + (size_t)b * SEQL * CONVD;
    const float* dtp = dtv + (size_t)b * SEQL * NH + hh;
    float* yp = (nq == 0 ? ya : nq == 1 ? yb : nq == 2 ? yc : yd)
                + (size_t)b * SEQL * DI + hh * HD + p;
    const int boff = DI + nq * 16;
    for (int t = 0; t < SEQL; t++) {
        const float* row = xb + (size_t)t * CONVD;
        float dt = __ldg(dtp + (size_t)t * NH);
        float dA = __expf(dt * A);
        float x = __ldg(row + hh * HD + p);
        float dx = dt * x;
        float4 B0 = __ldg(reinterpret_cast<const float4*>(row + boff));
        float4 B1 = __ldg(reinterpret_cast<const float4*>(row + boff + 4));
        float4 B2 = __ldg(reinterpret_cast<const float4*>(row + boff + 8));
        float4 B3 = __ldg(reinterpret_cast<const float4*>(row + boff + 12));
        float4 C0 = __ldg(reinterpret_cast<const float4*>(row + boff + DS));
        float4 C1 = __ldg(reinterpret_cast<const float4*>(row + boff + DS + 4));
        float4 C2 = __ldg(reinterpret_cast<const float4*>(row + boff + DS + 8));
        float4 C3 = __ldg(reinterpret_cast<const float4*>(row + boff + DS + 12));
        float y = 0.f;
        h[0]  = fmaf(h[0],  dA, dx * B0.x); y = fmaf(h[0],  C0.x, y);
        h[1]  = fmaf(h[1],  dA, dx * B0.y); y = fmaf(h[1],  C0.y, y);
        h[2]  = fmaf(h[2],  dA, dx * B0.z); y = fmaf(h[2],  C0.z, y);
        h[3]  = fmaf(h[3],  dA, dx * B0.w); y = fmaf(h[3],  C0.w, y);
        h[4]  = fmaf(h[4],  dA, dx * B1.x); y = fmaf(h[4],  C1.x, y);
        h[5]  = fmaf(h[5],  dA, dx * B1.y); y = fmaf(h[5],  C1.y, y);
        h[6]  = fmaf(h[6],  dA, dx * B1.z); y = fmaf(h[6],  C1.z, y);
        h[7]  = fmaf(h[7],  dA, dx * B1.w); y = fmaf(h[7],  C1.w, y);
        h[8]  = fmaf(h[8],  dA, dx * B2.x); y = fmaf(h[8],  C2.x, y);
        h[9]  = fmaf(h[9],  dA, dx * B2.y); y = fmaf(h[9],  C2.y, y);
        h[10] = fmaf(h[10], dA, dx * B2.z); y = fmaf(h[10], C2.z, y);
        h[11] = fmaf(h[11], dA, dx * B2.w); y = fmaf(h[11], C2.w, y);
        h[12] = fmaf(h[12], dA, dx * B3.x); y = fmaf(h[12], C3.x, y);
        h[13] = fmaf(h[13], dA, dx * B3.y); y = fmaf(h[13], C3.y, y);
        h[14] = fmaf(h[14], dA, dx * B3.z); y = fmaf(h[14], C3.z, y);
        h[15] = fmaf(h[15], dA, dx * B3.w); y = fmaf(h[15], C3.w, y);
        if (nq == 0) y = fmaf(Dh, x, y);
        yp[(size_t)t * DI] = y;
    }
}

// ---------------- gated RMSNorm over DI=2048 (sums 4 scan partials) ----------------
__global__ void rms_gate_kernel(const float* __restrict__ ya, const float* __restrict__ yb,
                                const float* __restrict__ yc, const float* __restrict__ yd,
                                const float* __restrict__ zx,
                                const float* __restrict__ nw, float* __restrict__ out) {
    __shared__ float smem[32];
    int row = blockIdx.x;
    float v[8];
    float s = 0.f;
    #pragma unroll
    for (int i = 0; i < 8; i++) {
        int c = threadIdx.x + i * 256;
        size_t o = (size_t)row * DI + c;
        float z = zx[(size_t)row * DIP + c];
        float g = z * (1.f / (1.f + __expf(-z)));
        float vv = ((ya[o] + yb[o]) + (yc[o] + yd[o])) * g;
        v[i] = vv;
        s += vv * vv;
    }
    float ms = block_reduce_sum(s, smem) * (1.f / DI);
    float rs = rsqrtf(ms + EPSV);
    #pragma unroll
    for (int i = 0; i < 8; i++) {
        int c = threadIdx.x + i * 256;
        out[(size_t)row * DI + c] = roundtf(v[i] * rs * nw[c]);
    }
}

// ---------------- launch ----------------
extern "C" void kernel_launch(void* const* d_in, const int* in_sizes, int n_in,
                              void* d_out, int out_size) {
    const float* x        = (const float*)d_in[0];
    const float* ln1_w    = (const float*)d_in[1];
    const float* ln1_b    = (const float*)d_in[2];
    const float* in_proj  = (const float*)d_in[3];
    const float* conv_w   = (const float*)d_in[4];
    const float* conv_b   = (const float*)d_in[5];
    const float* dt_bias  = (const float*)d_in[6];
    const float* A_log    = (const float*)d_in[7];
    const float* Dv       = (const float*)d_in[8];
    const float* norm_w   = (const float*)d_in[9];
    const float* out_proj = (const float*)d_in[10];
    const float* ln2_w    = (const float*)d_in[11];
    const float* ln2_b    = (const float*)d_in[12];
    const float* mlp_w1   = (const float*)d_in[13];
    const float* mlp_b1   = (const float*)d_in[14];
    const float* mlp_w2   = (const float*)d_in[15];
    const float* mlp_b2   = (const float*)d_in[16];
    float* out = (float*)d_out;

    float *p_ln1, *p_zx, *p_xbc, *p_dt, *p_ya, *p_yb, *p_yc, *p_yd;
    float *p_yn, *p_x1, *p_h2, *p_mid, *p_wip, *p_wop, *p_w1, *p_w2;
    cudaGetSymbolAddress((void**)&p_ln1, g_ln1);
    cudaGetSymbolAddress((void**)&p_zx, g_zx);
    cudaGetSymbolAddress((void**)&p_xbc, g_xbc);
    cudaGetSymbolAddress((void**)&p_dt, g_dt);
    cudaGetSymbolAddress((void**)&p_ya, g_ya);
    cudaGetSymbolAddress((void**)&p_yb, g_yb);
    cudaGetSymbolAddress((void**)&p_yc, g_yc);
    cudaGetSymbolAddress((void**)&p_yd, g_yd);
    cudaGetSymbolAddress((void**)&p_yn, g_yn);
    cudaGetSymbolAddress((void**)&p_x1, g_x1);
    cudaGetSymbolAddress((void**)&p_h2, g_h2);
    cudaGetSymbolAddress((void**)&p_mid, g_mid);
    cudaGetSymbolAddress((void**)&p_wip, g_wip);
    cudaGetSymbolAddress((void**)&p_wop, g_wop);
    cudaGetSymbolAddress((void**)&p_w1, g_w1);
    cudaGetSymbolAddress((void**)&p_w2, g_w2);

    cudaFuncSetAttribute(gemm_tc_kernel,
                         cudaFuncAttributeMaxDynamicSharedMemorySize, GEMM_SMEM_BYTES);

    // 0. pre-round weights to tf32-exact fp32
    {
        int n4;
        n4 = DIP * DM / 4;  round_tf32_kernel<<<(n4 + 255) / 256, 256>>>(in_proj, p_wip, n4);
        n4 = DM * DI / 4;   round_tf32_kernel<<<(n4 + 255) / 256, 256>>>(out_proj, p_wop, n4);
        n4 = DMLP * DM / 4; round_tf32_kernel<<<(n4 + 255) / 256, 256>>>(mlp_w1, p_w1, n4);
        n4 = DM * DMLP / 4; round_tf32_kernel<<<(n4 + 255) / 256, 256>>>(mlp_w2, p_w2, n4);
    }
    // 1. LN1 (rounded output)
    ln_kernel<<<TOK, 256>>>(x, ln1_w, ln1_b, p_ln1);
    // 2. in_proj: [4096,1024] @ [4256,1024]^T -> [4096,4256]
    gemm_tc_kernel<<<dim3((DIP + 127) / 128, TOK / 128), 256, GEMM_SMEM_BYTES>>>(
        p_ln1, p_wip, p_zx, TOK, DIP, DM, nullptr, nullptr, 0);
    // 3. conv + silu (float4)
    {
        int total = TOK * CONVD / 4;
        conv_silu_kernel<<<(total + 255) / 256, 256>>>(p_zx, conv_w, conv_b, p_xbc);
    }
    // 4. dt
    dt_kernel<<<(TOK * NH + 255) / 256, 256>>>(p_zx, dt_bias, p_dt);
    // 5. selective scan: 512 single-warp blocks, register-resident states
    scan_kernel<<<BATCH * NH * 8, 32>>>(p_xbc, p_dt, A_log, Dv, p_ya, p_yb, p_yc, p_yd);
    // 6. gated rmsnorm (sums 4 partials, rounded output)
    rms_gate_kernel<<<TOK, 256>>>(p_ya, p_yb, p_yc, p_yd, p_zx, norm_w, p_yn);
    // 7. out_proj + residual(x) -> x1
    gemm_tc_kernel<<<dim3(DM / 128, TOK / 128), 256, GEMM_SMEM_BYTES>>>(
        p_yn, p_wop, p_x1, TOK, DM, DI, nullptr, x, 0);
    // 8. LN2 (rounded output)
    ln_kernel<<<TOK, 256>>>(p_x1, ln2_w, ln2_b, p_h2);
    // 9. MLP1 + bias + gelu (rounded output)
    gemm_tc_kernel<<<dim3(DMLP / 128, TOK / 128), 256, GEMM_SMEM_BYTES>>>(
        p_h2, p_w1, p_mid, TOK, DMLP, DM, mlp_b1, nullptr, 1);
    // 10. MLP2 + bias + residual(x1) -> out
    gemm_tc_kernel<<<dim3(DM / 128, TOK / 128), 256, GEMM_SMEM_BYTES>>>(
        p_mid, p_w2, out, TOK, DM, DMLP, mlp_b2, p_x1, 0);
}